// round 1
// baseline (speedup 1.0000x reference)
#include <cuda_runtime.h>

// FractalDimensionModule: differential box-counting fractal dimension.
// Image 512x512 f32, windows 64x64 stride 4 -> 113x113 outputs.
// All box levels (s=4..64) are aligned to the 4-pixel grid, so we build a
// per-block local 4x4-tile max/min pyramid in shared memory and compute all
// 5 level sums per window, then the log-log regression slope.

#define IMG_W 512
#define OH    113
#define NB    15      // 15x15 blocks, 8x8 windows each (120 >= 113)

__global__ __launch_bounds__(256)
void fd_kernel(const float* __restrict__ img, float* __restrict__ out)
{
    // Level l covers box size s = 4<<l. Local 4-grid extents needed:
    // L0:23  L1:22  L2:20  L3:16  L4:8   (pad cols to 24)
    __shared__ float sMax[5][23][24];
    __shared__ float sMin[5][23][24];   // becomes diff (max-min) in phase 3

    const int tid = threadIdx.x;
    const int bx = blockIdx.x, by = blockIdx.y;
    const int R0 = 32 * by;   // region base pixel row
    const int C0 = 32 * bx;   // region base pixel col

    // ---- Phase 1: 4x4 tile max/min over the 23x23 local grid ----
    for (int t = tid; t < 23 * 23; t += 256) {
        const int r = t / 23, c = t % 23;
        int cb = C0 + 4 * c; if (cb > IMG_W - 4) cb = IMG_W - 4;   // clamp (edge blocks)
        float mx = -3.0e38f, mn = 3.0e38f;
        #pragma unroll
        for (int k = 0; k < 4; k++) {
            int rr = R0 + 4 * r + k; if (rr > 511) rr = 511;
            const float4 v = *reinterpret_cast<const float4*>(img + rr * IMG_W + cb);
            mx = fmaxf(mx, fmaxf(fmaxf(v.x, v.y), fmaxf(v.z, v.w)));
            mn = fminf(mn, fminf(fminf(v.x, v.y), fminf(v.z, v.w)));
        }
        sMax[0][r][c] = mx;
        sMin[0][r][c] = mn;
    }
    __syncthreads();

    // ---- Phase 2: pyramid. Level l from l-1 via dilated 2x2, dilation 1<<(l-1) ----
    const int Nl0 = 23, Nl1 = 22, Nl2 = 20, Nl3 = 16, Nl4 = 8;
    {
        // l = 1, d = 1
        for (int t = tid; t < Nl1 * Nl1; t += 256) {
            const int r = t / Nl1, c = t % Nl1;
            sMax[1][r][c] = fmaxf(fmaxf(sMax[0][r][c],   sMax[0][r+1][c]),
                                  fmaxf(sMax[0][r][c+1], sMax[0][r+1][c+1]));
            sMin[1][r][c] = fminf(fminf(sMin[0][r][c],   sMin[0][r+1][c]),
                                  fminf(sMin[0][r][c+1], sMin[0][r+1][c+1]));
        }
        __syncthreads();
        // l = 2, d = 2
        for (int t = tid; t < Nl2 * Nl2; t += 256) {
            const int r = t / Nl2, c = t % Nl2;
            sMax[2][r][c] = fmaxf(fmaxf(sMax[1][r][c],   sMax[1][r+2][c]),
                                  fmaxf(sMax[1][r][c+2], sMax[1][r+2][c+2]));
            sMin[2][r][c] = fminf(fminf(sMin[1][r][c],   sMin[1][r+2][c]),
                                  fminf(sMin[1][r][c+2], sMin[1][r+2][c+2]));
        }
        __syncthreads();
        // l = 3, d = 4
        for (int t = tid; t < Nl3 * Nl3; t += 256) {
            const int r = t / Nl3, c = t % Nl3;
            sMax[3][r][c] = fmaxf(fmaxf(sMax[2][r][c],   sMax[2][r+4][c]),
                                  fmaxf(sMax[2][r][c+4], sMax[2][r+4][c+4]));
            sMin[3][r][c] = fminf(fminf(sMin[2][r][c],   sMin[2][r+4][c]),
                                  fminf(sMin[2][r][c+4], sMin[2][r+4][c+4]));
        }
        __syncthreads();
        // l = 4, d = 8
        for (int t = tid; t < Nl4 * Nl4; t += 256) {
            const int r = t / Nl4, c = t % Nl4;
            sMax[4][r][c] = fmaxf(fmaxf(sMax[3][r][c],   sMax[3][r+8][c]),
                                  fmaxf(sMax[3][r][c+8], sMax[3][r+8][c+8]));
            sMin[4][r][c] = fminf(fminf(sMin[3][r][c],   sMin[3][r+8][c]),
                                  fminf(sMin[3][r][c+8], sMin[3][r+8][c+8]));
        }
        __syncthreads();
    }

    // ---- Phase 3: diff = max - min, in place over sMin ----
    {
        const int n[5] = {Nl0, Nl1, Nl2, Nl3, Nl4};
        #pragma unroll
        for (int l = 0; l < 5; l++) {
            const int nl = n[l];
            for (int t = tid; t < nl * nl; t += 256) {
                const int r = t / nl, c = t % nl;
                sMin[l][r][c] = sMax[l][r][c] - sMin[l][r][c];
            }
        }
    }
    __syncthreads();

    // ---- Phase 4: per-window dilated box sums, 4 threads per window ----
    const int w  = tid >> 2;        // window 0..63
    const int p  = tid & 3;         // partial id 0..3
    const int wi = w >> 3;          // local window row 0..7
    const int wj = w & 7;           // local window col 0..7

    float d4 = 0.f, d8 = 0.f, d16 = 0.f, d32 = 0.f, d64 = 0.f;

    // s=4 : 16x16 taps, spacing 1. p takes rows 4p..4p+3.
    #pragma unroll
    for (int a = 0; a < 4; a++) {
        const int ti = 4 * p + a;
        #pragma unroll
        for (int tj = 0; tj < 16; tj++)
            d4 += sMin[0][wi + ti][wj + tj];
    }
    // s=8 : 8x8 taps, spacing 2. p takes rows {4p, 4p+2}.
    #pragma unroll
    for (int a = 0; a < 2; a++) {
        const int ti = 4 * p + 2 * a;
        #pragma unroll
        for (int b = 0; b < 8; b++)
            d8 += sMin[1][wi + ti][wj + 2 * b];
    }
    // s=16 : 4x4 taps, spacing 4. p takes row 4p.
    #pragma unroll
    for (int b = 0; b < 4; b++)
        d16 += sMin[2][wi + 4 * p][wj + 4 * b];
    // s=32 : 2x2 taps, spacing 8. p<2 take row 8p.
    if (p < 2)
        d32 = sMin[3][wi + 8 * p][wj] + sMin[3][wi + 8 * p][wj + 8];
    // s=64 : single tap.
    if (p == 0)
        d64 = sMin[4][wi][wj];

    // quad reduction (lanes of a window are consecutive)
    d4  += __shfl_xor_sync(0xffffffffu, d4,  1);
    d4  += __shfl_xor_sync(0xffffffffu, d4,  2);
    d8  += __shfl_xor_sync(0xffffffffu, d8,  1);
    d8  += __shfl_xor_sync(0xffffffffu, d8,  2);
    d16 += __shfl_xor_sync(0xffffffffu, d16, 1);
    d16 += __shfl_xor_sync(0xffffffffu, d16, 2);
    d32 += __shfl_xor_sync(0xffffffffu, d32, 1);
    d32 += __shfl_xor_sync(0xffffffffu, d32, 2);

    if (p == 0) {
        const int gi = 8 * by + wi;
        const int gj = 8 * bx + wj;
        if (gi < OH && gj < OH) {
            // log sizes for s = 64,32,16,8,4
            const float ls0 = 4.15888308336f;   // ln 64
            const float ls1 = 3.46573590280f;   // ln 32
            const float ls2 = 2.77258872224f;   // ln 16
            const float ls3 = 2.07944154168f;   // ln 8
            const float ls4 = 1.38629436112f;   // ln 4
            const float S2  = ls0*ls0 + ls1*ls1 + ls2*ls2 + ls3*ls3 + ls4*ls4;
            const float num = ls0 * logf(d64) + ls1 * logf(d32) + ls2 * logf(d16)
                            + ls3 * logf(d8)  + ls4 * logf(d4);
            out[gi * OH + gj] = -num / S2;
        }
    }
}

extern "C" void kernel_launch(void* const* d_in, const int* in_sizes, int n_in,
                              void* d_out, int out_size)
{
    const float* img = (const float*)d_in[0];   // (1,1,512,512) f32
    float* out = (float*)d_out;                 // (1,1,113,113) f32
    dim3 grid(NB, NB);
    fd_kernel<<<grid, 256>>>(img, out);
}

// round 4
// speedup vs baseline: 1.7744x; 1.7744x over previous
#include <cuda_runtime.h>

// Differential box-counting fractal dimension, 512x512 f32 image,
// 64x64 windows stride 4 -> 113x113 outputs.
// Per block: 8x8 windows. Build 4x4-tile max/min pyramid in smem, then
// SEPARABLE window sums (shared row-sums, then short vertical sums).

#define IMG_W 512
#define OH    113
#define NB    15

__global__ __launch_bounds__(256)
void fd_kernel(const float* __restrict__ img, float* __restrict__ out)
{
    // Pyramid levels, local 4-grid extents: L0:23 L1:22 L2:20 L3:16 L4:8
    __shared__ float sMax[5][23][24];
    __shared__ float sMin[5][23][24];   // levels 0..2 become diff in-place
    __shared__ float rs0[23][8];        // level-0 horizontal 16-sums
    __shared__ float rs1[22][8];        // level-1 horizontal 8-sums (stride 2)
    __shared__ float rs2[20][8];        // level-2 horizontal 4-sums (stride 4)

    const int tid = threadIdx.x;
    const int bx = blockIdx.x, by = blockIdx.y;
    const int R0 = 32 * by;
    const int C0 = 32 * bx;

    // ---- Phase 1: 4x4 tile max/min over 23x23 local grid ----
    for (int t = tid; t < 23 * 23; t += 256) {
        const int r = t / 23, c = t % 23;
        int cb = C0 + 4 * c; if (cb > IMG_W - 4) cb = IMG_W - 4;
        float mx = -3.0e38f, mn = 3.0e38f;
        #pragma unroll
        for (int k = 0; k < 4; k++) {
            int rr = R0 + 4 * r + k; if (rr > 511) rr = 511;
            const float4 v = *reinterpret_cast<const float4*>(img + rr * IMG_W + cb);
            mx = fmaxf(mx, fmaxf(fmaxf(v.x, v.y), fmaxf(v.z, v.w)));
            mn = fminf(mn, fminf(fminf(v.x, v.y), fminf(v.z, v.w)));
        }
        sMax[0][r][c] = mx;
        sMin[0][r][c] = mn;
    }
    __syncthreads();

    // ---- Phase 2: pyramid (dilated 2x2, dilation 1<<(l-1)) ----
    for (int t = tid; t < 22 * 22; t += 256) {
        const int r = t / 22, c = t % 22;
        sMax[1][r][c] = fmaxf(fmaxf(sMax[0][r][c],   sMax[0][r+1][c]),
                              fmaxf(sMax[0][r][c+1], sMax[0][r+1][c+1]));
        sMin[1][r][c] = fminf(fminf(sMin[0][r][c],   sMin[0][r+1][c]),
                              fminf(sMin[0][r][c+1], sMin[0][r+1][c+1]));
    }
    __syncthreads();
    for (int t = tid; t < 20 * 20; t += 256) {
        const int r = t / 20, c = t % 20;
        sMax[2][r][c] = fmaxf(fmaxf(sMax[1][r][c],   sMax[1][r+2][c]),
                              fmaxf(sMax[1][r][c+2], sMax[1][r+2][c+2]));
        sMin[2][r][c] = fminf(fminf(sMin[1][r][c],   sMin[1][r+2][c]),
                              fminf(sMin[1][r][c+2], sMin[1][r+2][c+2]));
    }
    __syncthreads();
    for (int t = tid; t < 16 * 16; t += 256) {
        const int r = t / 16, c = t % 16;
        sMax[3][r][c] = fmaxf(fmaxf(sMax[2][r][c],   sMax[2][r+4][c]),
                              fmaxf(sMax[2][r][c+4], sMax[2][r+4][c+4]));
        sMin[3][r][c] = fminf(fminf(sMin[2][r][c],   sMin[2][r+4][c]),
                              fminf(sMin[2][r][c+4], sMin[2][r+4][c+4]));
    }
    __syncthreads();
    if (tid < 64) {
        const int r = tid >> 3, c = tid & 7;
        sMax[4][r][c] = fmaxf(fmaxf(sMax[3][r][c],   sMax[3][r+8][c]),
                              fmaxf(sMax[3][r][c+8], sMax[3][r+8][c+8]));
        sMin[4][r][c] = fminf(fminf(sMin[3][r][c],   sMin[3][r+8][c]),
                              fminf(sMin[3][r][c+8], sMin[3][r+8][c+8]));
    }
    __syncthreads();

    // ---- Phase 3: diff = max - min in place, levels 0..2 only ----
    for (int t = tid; t < 23 * 23; t += 256) {
        const int r = t / 23, c = t % 23;
        sMin[0][r][c] = sMax[0][r][c] - sMin[0][r][c];
    }
    for (int t = tid; t < 22 * 22; t += 256) {
        const int r = t / 22, c = t % 22;
        sMin[1][r][c] = sMax[1][r][c] - sMin[1][r][c];
    }
    for (int t = tid; t < 20 * 20; t += 256) {
        const int r = t / 20, c = t % 20;
        sMin[2][r][c] = sMax[2][r][c] - sMin[2][r][c];
    }
    __syncthreads();

    // ---- Phase 4a: shared horizontal row-sums ----
    // rs0: 23*8=184 outputs (16 dense taps)
    // rs1: 22*8=176 outputs (8 taps, stride 2)
    // rs2: 20*8=160 outputs (4 taps, stride 4)   total 520
    for (int o = tid; o < 520; o += 256) {
        if (o < 184) {
            const int r = o >> 3, wj = o & 7;
            float s = 0.f;
            #pragma unroll
            for (int t = 0; t < 16; t++) s += sMin[0][r][wj + t];
            rs0[r][wj] = s;
        } else if (o < 360) {
            const int q = o - 184;
            const int r = q >> 3, wj = q & 7;
            float s = 0.f;
            #pragma unroll
            for (int b = 0; b < 8; b++) s += sMin[1][r][wj + 2 * b];
            rs1[r][wj] = s;
        } else {
            const int q = o - 360;
            const int r = q >> 3, wj = q & 7;
            float s = 0.f;
            #pragma unroll
            for (int b = 0; b < 4; b++) s += sMin[2][r][wj + 4 * b];
            rs2[r][wj] = s;
        }
    }
    __syncthreads();

    // ---- Phase 4b: one thread per window — vertical sums + regression ----
    if (tid < 64) {
        const int wi = tid >> 3, wj = tid & 7;
        const int gi = 8 * by + wi;
        const int gj = 8 * bx + wj;
        if (gi < OH && gj < OH) {
            float d4 = 0.f, d8 = 0.f, d16 = 0.f;
            #pragma unroll
            for (int a = 0; a < 16; a++) d4  += rs0[wi + a][wj];
            #pragma unroll
            for (int a = 0; a < 8;  a++) d8  += rs1[wi + 2 * a][wj];
            #pragma unroll
            for (int a = 0; a < 4;  a++) d16 += rs2[wi + 4 * a][wj];
            const float d32 =
                (sMax[3][wi][wj]     - sMin[3][wi][wj])     +
                (sMax[3][wi][wj+8]   - sMin[3][wi][wj+8])   +
                (sMax[3][wi+8][wj]   - sMin[3][wi+8][wj])   +
                (sMax[3][wi+8][wj+8] - sMin[3][wi+8][wj+8]);
            const float d64 = sMax[4][wi][wj] - sMin[4][wi][wj];

            const float ls0 = 4.15888308336f;   // ln 64
            const float ls1 = 3.46573590280f;   // ln 32
            const float ls2 = 2.77258872224f;   // ln 16
            const float ls3 = 2.07944154168f;   // ln 8
            const float ls4 = 1.38629436112f;   // ln 4
            const float S2  = ls0*ls0 + ls1*ls1 + ls2*ls2 + ls3*ls3 + ls4*ls4;
            const float num = ls0 * __logf(d64) + ls1 * __logf(d32)
                            + ls2 * __logf(d16) + ls3 * __logf(d8)
                            + ls4 * __logf(d4);
            out[gi * OH + gj] = -num / S2;
        }
    }
}

extern "C" void kernel_launch(void* const* d_in, const int* in_sizes, int n_in,
                              void* d_out, int out_size)
{
    const float* img = (const float*)d_in[0];   // (1,1,512,512) f32
    float* out = (float*)d_out;                 // (1,1,113,113) f32
    dim3 grid(NB, NB);
    fd_kernel<<<grid, 256>>>(img, out);
}

// round 5
// speedup vs baseline: 2.1852x; 1.2315x over previous
#include <cuda_runtime.h>

// Differential box-counting fractal dimension, 512x512 f32, 64x64 windows
// stride 4 -> 113x113. One block per OUTPUT ROW (113 blocks = one wave).
// All windows in a row share the same 64 pixel rows, so every level's
// vertical sum spans the full extent -> fold diff into column sums, then
// each window is a short horizontal sum.

#define OH 113

__global__ __launch_bounds__(512)
void fd_kernel(const float* __restrict__ img, float* __restrict__ out)
{
    // L0: 16x128 4x4-tile max/min. L1: even rows only (8x127).
    // L2: rows {0,4,8,12} (4x125). L3: rows {0,8} (2x121). Cols padded to 128.
    __shared__ float M0[16][128], N0[16][128];
    __shared__ float M1[8][128],  N1[8][128];
    __shared__ float M2[4][128],  N2[4][128];
    __shared__ float M3[2][128],  N3[2][128];
    __shared__ float cs0[128], cs1[128], cs2[128];

    const int tid = threadIdx.x;
    const int gi  = blockIdx.x;        // output row 0..112
    const int R0  = 4 * gi;            // top pixel row (R0+63 <= 511)

    // ---- P1: 4x4 pixel-tile max/min, 16x128 grid (4 items/thread) ----
    #pragma unroll
    for (int it = 0; it < 4; it++) {
        const int idx = tid + it * 512;          // 0..2047
        const int r = idx >> 7, c = idx & 127;
        const float* p = img + (R0 + 4 * r) * 512 + 4 * c;
        float mx = -3.0e38f, mn = 3.0e38f;
        #pragma unroll
        for (int k = 0; k < 4; k++) {
            const float4 v = *reinterpret_cast<const float4*>(p + k * 512);
            mx = fmaxf(mx, fmaxf(fmaxf(v.x, v.y), fmaxf(v.z, v.w)));
            mn = fminf(mn, fminf(fminf(v.x, v.y), fminf(v.z, v.w)));
        }
        M0[r][c] = mx;
        N0[r][c] = mn;
    }
    __syncthreads();

    // ---- P2: L1, even rows only: a<8 (row 2a), c<127 ----
    #pragma unroll
    for (int it = 0; it < 2; it++) {
        const int idx = tid + it * 512;
        if (idx < 8 * 127) {
            const int a = idx / 127, c = idx % 127;
            const int r = 2 * a;
            M1[a][c] = fmaxf(fmaxf(M0[r][c],   M0[r+1][c]),
                             fmaxf(M0[r][c+1], M0[r+1][c+1]));
            N1[a][c] = fminf(fminf(N0[r][c],   N0[r+1][c]),
                             fminf(N0[r][c+1], N0[r+1][c+1]));
        }
    }
    __syncthreads();

    // ---- P3: L2, rows {0,4,8,12} stored as a2<4, c<125 ----
    if (tid < 4 * 125) {
        const int a2 = tid / 125, c = tid % 125;
        const int a1 = 2 * a2;                    // L1 stored rows a1, a1+1
        M2[a2][c] = fmaxf(fmaxf(M1[a1][c],   M1[a1+1][c]),
                          fmaxf(M1[a1][c+2], M1[a1+1][c+2]));
        N2[a2][c] = fminf(fminf(N1[a1][c],   N1[a1+1][c]),
                          fminf(N1[a1][c+2], N1[a1+1][c+2]));
    }
    __syncthreads();

    // ---- P4+P5 fused: L3 max/min AND column sums (622 items) ----
    #pragma unroll
    for (int it = 0; it < 2; it++) {
        const int idx = tid + it * 512;
        if (idx < 242) {
            // L3 rows {0,8}: j<2, c<121; uses L2 stored rows 2j,2j+1, cols c,c+4
            const int j = idx / 121, c = idx % 121;
            const int a = 2 * j;
            M3[j][c] = fmaxf(fmaxf(M2[a][c],   M2[a+1][c]),
                             fmaxf(M2[a][c+4], M2[a+1][c+4]));
            N3[j][c] = fminf(fminf(N2[a][c],   N2[a+1][c]),
                             fminf(N2[a][c+4], N2[a+1][c+4]));
        } else if (idx < 370) {
            // cs0[c] = sum over 16 rows of (M0-N0)
            const int c = idx - 242;               // c < 128
            float s = 0.f;
            #pragma unroll
            for (int r = 0; r < 16; r++) s += M0[r][c] - N0[r][c];
            cs0[c] = s;
        } else if (idx < 497) {
            // cs1[c] = sum over 8 stored rows of (M1-N1), c < 127
            const int c = idx - 370;
            float s = 0.f;
            #pragma unroll
            for (int a = 0; a < 8; a++) s += M1[a][c] - N1[a][c];
            cs1[c] = s;
        } else if (idx < 622) {
            // cs2[c] = sum over 4 stored rows of (M2-N2), c < 125
            const int c = idx - 497;
            float s = 0.f;
            #pragma unroll
            for (int a = 0; a < 4; a++) s += M2[a][c] - N2[a][c];
            cs2[c] = s;
        }
    }
    __syncthreads();

    // ---- P6: per-window horizontal sums + regression (113 threads) ----
    if (tid < OH) {
        const int wj = tid;
        float d4 = 0.f, d8 = 0.f, d16 = 0.f;
        #pragma unroll
        for (int t = 0; t < 16; t++) d4  += cs0[wj + t];
        #pragma unroll
        for (int b = 0; b < 8;  b++) d8  += cs1[wj + 2 * b];
        #pragma unroll
        for (int b = 0; b < 4;  b++) d16 += cs2[wj + 4 * b];

        const float d32 = (M3[0][wj]   - N3[0][wj])
                        + (M3[1][wj]   - N3[1][wj])
                        + (M3[0][wj+8] - N3[0][wj+8])
                        + (M3[1][wj+8] - N3[1][wj+8]);
        const float d64 = fmaxf(fmaxf(M3[0][wj], M3[1][wj]),
                                fmaxf(M3[0][wj+8], M3[1][wj+8]))
                        - fminf(fminf(N3[0][wj], N3[1][wj]),
                                fminf(N3[0][wj+8], N3[1][wj+8]));

        const float ls0 = 4.15888308336f;   // ln 64
        const float ls1 = 3.46573590280f;   // ln 32
        const float ls2 = 2.77258872224f;   // ln 16
        const float ls3 = 2.07944154168f;   // ln 8
        const float ls4 = 1.38629436112f;   // ln 4
        const float S2  = ls0*ls0 + ls1*ls1 + ls2*ls2 + ls3*ls3 + ls4*ls4;
        const float num = ls0 * __logf(d64) + ls1 * __logf(d32)
                        + ls2 * __logf(d16) + ls3 * __logf(d8)
                        + ls4 * __logf(d4);
        out[gi * OH + wj] = -num / S2;
    }
}

extern "C" void kernel_launch(void* const* d_in, const int* in_sizes, int n_in,
                              void* d_out, int out_size)
{
    const float* img = (const float*)d_in[0];   // (1,1,512,512) f32
    float* out = (float*)d_out;                 // (1,1,113,113) f32
    fd_kernel<<<OH, 512>>>(img, out);
}